// round 4
// baseline (speedup 1.0000x reference)
#include <cuda_runtime.h>
#include <cstdint>

// Problem constants (fixed by the reference setup)
#define NB 65536        // batch rows
#define NF 512          // in_features
#define NK 1299         // number of centers
#define THREADS 512
#define WARPS_PER_BLOCK (THREADS / 32)        // 16
#define NBLOCKS (NB / WARPS_PER_BLOCK)        // 4096 blocks, 1 warp per row

// Scratch for deterministic loss reduction (no device allocs allowed)
__device__ float        g_partials[NBLOCKS];
__device__ unsigned int g_ticket = 0;          // reset by last block each launch

__global__ __launch_bounds__(THREADS)
void fused_kernel(const float* __restrict__ input,
                  const float* __restrict__ factor,
                  const int* __restrict__ label,     // JAX downcasts int64->int32
                  const float* __restrict__ centers,
                  float* __restrict__ out)           // out[0]=loss, out[1..NB]=predict_a
{
    const int warp = threadIdx.x >> 5;
    const int lane = threadIdx.x & 31;
    const int b = blockIdx.x * WARPS_PER_BLOCK + warp;

    const float4* in4 = reinterpret_cast<const float4*>(input + (size_t)b * NF);
    int c = label[b];
    c = (c < 0) ? 0 : (c >= NK ? NK - 1 : c);          // in-bounds insurance
    const float4* ce4 = reinterpret_cast<const float4*>(centers + (size_t)c * NF);

    // input: streamed once -> evict-first; centers: 2.6 MB table, keep in L2.
    float acc = 0.0f;
#pragma unroll
    for (int i = 0; i < 4; i++) {
        float4 a = __ldcs(&in4[lane + 32 * i]);
        float4 w = __ldg(&ce4[lane + 32 * i]);
        acc += a.x * w.x + a.y * w.y + a.z * w.z + a.w * w.w;
    }

    // Warp reduction
#pragma unroll
    for (int o = 16; o; o >>= 1)
        acc += __shfl_xor_sync(0xffffffffu, acc, o);

    __shared__ float s_loss[WARPS_PER_BLOCK];
    if (lane == 0) {
        float p = 12.0f * tanhf(acc);
        __stcs(&out[1 + b], p);                        // streamed output
        float d = p - __ldg(&factor[b]);
        float ad = fabsf(d);
        s_loss[warp] = (ad < 1.0f) ? 0.5f * d * d : (ad - 0.5f);
    }
    __syncthreads();

    // Warp 0 reduces the 16 per-warp terms, publishes the block partial.
    __shared__ bool s_is_last;
    if (warp == 0) {
        float t = (lane < WARPS_PER_BLOCK) ? s_loss[lane] : 0.0f;
#pragma unroll
        for (int o = 8; o; o >>= 1)
            t += __shfl_xor_sync(0xffffffffu, t, o);
        if (lane == 0) {
            g_partials[blockIdx.x] = t;
            __threadfence();
            unsigned int ticket = atomicAdd(&g_ticket, 1u);
            s_is_last = (ticket == (unsigned int)(gridDim.x - 1));
        }
    }
    __syncthreads();

    // Last block: deterministic tree-reduce of all partials (fixed order).
    if (s_is_last) {
        __shared__ float s[THREADS];
        float t = 0.0f;
        for (int i = threadIdx.x; i < NBLOCKS; i += THREADS)
            t += g_partials[i];
        s[threadIdx.x] = t;
        __syncthreads();
#pragma unroll
        for (int o = THREADS / 2; o; o >>= 1) {
            if (threadIdx.x < o) s[threadIdx.x] += s[threadIdx.x + o];
            __syncthreads();
        }
        if (threadIdx.x == 0) {
            out[0] = s[0] * (1.0f / (float)NB);
            g_ticket = 0;                               // clean state for next replay
        }
    }
}

extern "C" void kernel_launch(void* const* d_in, const int* in_sizes, int n_in,
                              void* d_out, int out_size)
{
    // metadata order follows setup_inputs: input, factor, label, centers
    const float* input   = (const float*)d_in[0];
    const float* factor  = (const float*)d_in[1];
    const int*   label   = (const int*)d_in[2];
    const float* centers = (const float*)d_in[3];

    float* out = (float*)d_out;   // out[0]=loss, out[1..NB]=predict_a

    fused_kernel<<<NBLOCKS, THREADS>>>(input, factor, label, centers, out);
}